// round 2
// baseline (speedup 1.0000x reference)
#include <cuda_runtime.h>

#define NUM_USERS 100000
#define NUM_ITEMS 100000
#define N_NODES   200000
#define EMB       64
#define N_EDGES   3200000
#define SCAN_CHUNK 1024
#define NB ((N_NODES + SCAN_CHUNK - 1) / SCAN_CHUNK)   // 196

// ---------------- scratch (no allocations allowed) ----------------
__device__ int   g_cnt[N_NODES];
__device__ int   g_off[N_NODES];     // exclusive row offsets after scan3
__device__ int   g_cur[N_NODES];     // scatter cursors
__device__ int   g_bsum[NB];
__device__ __align__(16) int   g_scol[N_EDGES];    // cols sorted by row
__device__ __align__(16) float g_sw[N_EDGES];      // weights sorted by row
__device__ __align__(16) float g_buf0[(size_t)N_NODES * EMB];
__device__ __align__(16) float g_buf1[(size_t)N_NODES * EMB];

// ---------------- init: build ego = concat(user,item); zero histogram ------
__global__ void k_init(const float* __restrict__ user, const float* __restrict__ item) {
    int i = blockIdx.x * blockDim.x + threadIdx.x;
    int stride = gridDim.x * blockDim.x;
    const int NV4 = (N_NODES * EMB) / 4;         // 3.2M float4
    const int UV4 = (NUM_USERS * EMB) / 4;
    float4* b0 = reinterpret_cast<float4*>(g_buf0);
    const float4* u4 = reinterpret_cast<const float4*>(user);
    const float4* t4 = reinterpret_cast<const float4*>(item);
    for (int j = i; j < NV4; j += stride)
        b0[j] = (j < UV4) ? u4[j] : t4[j - UV4];
    for (int j = i; j < N_NODES; j += stride)
        g_cnt[j] = 0;
}

// ---------------- histogram of edge_row ----------------
__global__ void k_hist(const int* __restrict__ edge_row) {
    int e = blockIdx.x * blockDim.x + threadIdx.x;
    if (e < N_EDGES)
        atomicAdd(&g_cnt[edge_row[e]], 1);
}

// ---------------- 3-kernel exclusive scan over g_cnt ----------------
__global__ void k_scan1() {
    __shared__ int s[SCAN_CHUNK];
    int tid = threadIdx.x;
    int gid = blockIdx.x * SCAN_CHUNK + tid;
    int v = (gid < N_NODES) ? g_cnt[gid] : 0;
    s[tid] = v;
    __syncthreads();
    for (int d = 1; d < SCAN_CHUNK; d <<= 1) {
        int t = (tid >= d) ? s[tid - d] : 0;
        __syncthreads();
        s[tid] += t;
        __syncthreads();
    }
    if (gid < N_NODES) g_off[gid] = s[tid];          // chunk-inclusive
    if (tid == SCAN_CHUNK - 1) g_bsum[blockIdx.x] = s[tid];
}

__global__ void k_scan2() {
    __shared__ int s[256];
    int tid = threadIdx.x;
    int v = (tid < NB) ? g_bsum[tid] : 0;
    s[tid] = v;
    __syncthreads();
    for (int d = 1; d < 256; d <<= 1) {
        int t = (tid >= d) ? s[tid - d] : 0;
        __syncthreads();
        s[tid] += t;
        __syncthreads();
    }
    if (tid < NB) g_bsum[tid] = s[tid] - v;          // exclusive block offsets
}

__global__ void k_scan3() {
    int i = blockIdx.x * blockDim.x + threadIdx.x;
    if (i < N_NODES) {
        int excl = g_off[i] - g_cnt[i] + g_bsum[i / SCAN_CHUNK];
        g_off[i] = excl;
        g_cur[i] = excl;
    }
}

// ---------------- scatter edges into CSR order ----------------
__global__ void k_scatter(const int* __restrict__ edge_row,
                          const int* __restrict__ edge_col,
                          const float* __restrict__ edge_w) {
    int e = blockIdx.x * blockDim.x + threadIdx.x;
    if (e < N_EDGES) {
        int r = edge_row[e];
        int pos = atomicAdd(&g_cur[r], 1);
        g_scol[pos] = edge_col[e];
        g_sw[pos]   = edge_w[e];
    }
}

// ---------------- CSR SpMM: one warp per row, fused acc/epilogue ----------
// Ping-pong buffers are selected at COMPILE TIME inside device code
// (device globals must not be passed as host-side kernel arguments).
// MODE 0: x=g_buf0 -> y=g_buf1; out  = ego1
// MODE 1: x=g_buf1 -> y=g_buf0; out += ego2
// MODE 2: x=g_buf0;             out  = (out + ego3)/3
template <int MODE>
__global__ __launch_bounds__(256) void k_spmm(float* __restrict__ out) {
    int warp = (blockIdx.x * blockDim.x + threadIdx.x) >> 5;
    int lane = threadIdx.x & 31;
    if (warp >= N_NODES) return;

    int start = g_off[warp];
    int end   = (warp == N_NODES - 1) ? N_EDGES : g_off[warp + 1];

    const float* xp = (MODE == 1) ? g_buf1 : g_buf0;
    const float2* __restrict__ x2 = reinterpret_cast<const float2*>(xp);
    float accx = 0.f, accy = 0.f;

    int e = start;
    // unroll x2 for memory-level parallelism on the row gathers
    for (; e + 1 < end; e += 2) {
        int   c0 = __ldg(&g_scol[e]);
        int   c1 = __ldg(&g_scol[e + 1]);
        float w0 = __ldg(&g_sw[e]);
        float w1 = __ldg(&g_sw[e + 1]);
        float2 a = __ldg(&x2[(size_t)c0 * 32 + lane]);
        float2 b = __ldg(&x2[(size_t)c1 * 32 + lane]);
        accx = fmaf(w0, a.x, accx);
        accy = fmaf(w0, a.y, accy);
        accx = fmaf(w1, b.x, accx);
        accy = fmaf(w1, b.y, accy);
    }
    if (e < end) {
        int   c0 = __ldg(&g_scol[e]);
        float w0 = __ldg(&g_sw[e]);
        float2 a = __ldg(&x2[(size_t)c0 * 32 + lane]);
        accx = fmaf(w0, a.x, accx);
        accy = fmaf(w0, a.y, accy);
    }

    size_t idx = (size_t)warp * 32 + lane;
    float2* out2 = reinterpret_cast<float2*>(out);
    float2 v; v.x = accx; v.y = accy;

    if (MODE == 0) {
        out2[idx] = v;
        reinterpret_cast<float2*>(g_buf1)[idx] = v;
    } else if (MODE == 1) {
        float2 o = out2[idx];
        o.x += accx; o.y += accy;
        out2[idx] = o;
        reinterpret_cast<float2*>(g_buf0)[idx] = v;
    } else {
        float2 o = out2[idx];
        const float s = 1.0f / 3.0f;
        o.x = (o.x + accx) * s;
        o.y = (o.y + accy) * s;
        out2[idx] = o;
    }
}

// ---------------- launch ----------------
extern "C" void kernel_launch(void* const* d_in, const int* in_sizes, int n_in,
                              void* d_out, int out_size) {
    const float* user_emb = (const float*)d_in[0];
    const float* item_emb = (const float*)d_in[1];
    const float* edge_w   = (const float*)d_in[2];
    const int*   edge_row = (const int*)d_in[3];
    const int*   edge_col = (const int*)d_in[4];
    float* out = (float*)d_out;

    // 1) ego = concat(user,item), zero histogram
    k_init<<<2048, 256>>>(user_emb, item_emb);

    // 2) histogram rows
    k_hist<<<(N_EDGES + 255) / 256, 256>>>(edge_row);

    // 3) exclusive scan -> row offsets + cursors
    k_scan1<<<NB, SCAN_CHUNK>>>();
    k_scan2<<<1, 256>>>();
    k_scan3<<<(N_NODES + 255) / 256, 256>>>();

    // 4) counting-sort scatter to CSR
    k_scatter<<<(N_EDGES + 255) / 256, 256>>>(edge_row, edge_col, edge_w);

    // 5) three SpMM layers, acc and /3 fused
    const int SPMM_BLOCKS = (N_NODES * 32 + 255) / 256;   // one warp per row
    k_spmm<0><<<SPMM_BLOCKS, 256>>>(out);
    k_spmm<1><<<SPMM_BLOCKS, 256>>>(out);
    k_spmm<2><<<SPMM_BLOCKS, 256>>>(out);
}

// round 3
// speedup vs baseline: 1.1110x; 1.1110x over previous
#include <cuda_runtime.h>
#include <cuda_fp16.h>

#define NUM_USERS 100000
#define NUM_ITEMS 100000
#define N_NODES   200000
#define EMB       64
#define N_EDGES   3200000
#define SCAN_CHUNK 1024
#define NB ((N_NODES + SCAN_CHUNK - 1) / SCAN_CHUNK)   // 196

// ---------------- scratch (no allocations allowed) ----------------
__device__ int  g_cnt[N_NODES];
__device__ int  g_off[N_NODES];
__device__ int  g_cur[N_NODES];
__device__ int  g_bsum[NB];
__device__ __align__(16) int2   g_edge[N_EDGES];               // {col, w-bits} sorted by row
__device__ __align__(16) __half g_h0[(size_t)N_NODES * EMB];   // fp16 ping
__device__ __align__(16) __half g_h1[(size_t)N_NODES * EMB];   // fp16 pong

// ---------------- init: ego = concat(user,item) -> fp16; zero histogram ----
__global__ void k_init(const float* __restrict__ user, const float* __restrict__ item) {
    int i = blockIdx.x * blockDim.x + threadIdx.x;
    int stride = gridDim.x * blockDim.x;
    const int NV4 = (N_NODES * EMB) / 4;         // groups of 4 floats
    const int UV4 = (NUM_USERS * EMB) / 4;
    const float4* u4 = reinterpret_cast<const float4*>(user);
    const float4* t4 = reinterpret_cast<const float4*>(item);
    uint2* h4 = reinterpret_cast<uint2*>(g_h0);  // 4 halves = 8 bytes
    for (int j = i; j < NV4; j += stride) {
        float4 f = (j < UV4) ? u4[j] : t4[j - UV4];
        __half2 a = __floats2half2_rn(f.x, f.y);
        __half2 b = __floats2half2_rn(f.z, f.w);
        uint2 p;
        p.x = *reinterpret_cast<unsigned*>(&a);
        p.y = *reinterpret_cast<unsigned*>(&b);
        h4[j] = p;
    }
    for (int j = i; j < N_NODES; j += stride)
        g_cnt[j] = 0;
}

// ---------------- histogram of edge_row ----------------
__global__ void k_hist(const int* __restrict__ edge_row) {
    int e = blockIdx.x * blockDim.x + threadIdx.x;
    if (e < N_EDGES)
        atomicAdd(&g_cnt[edge_row[e]], 1);
}

// ---------------- 3-kernel exclusive scan over g_cnt ----------------
__global__ void k_scan1() {
    __shared__ int s[SCAN_CHUNK];
    int tid = threadIdx.x;
    int gid = blockIdx.x * SCAN_CHUNK + tid;
    int v = (gid < N_NODES) ? g_cnt[gid] : 0;
    s[tid] = v;
    __syncthreads();
    for (int d = 1; d < SCAN_CHUNK; d <<= 1) {
        int t = (tid >= d) ? s[tid - d] : 0;
        __syncthreads();
        s[tid] += t;
        __syncthreads();
    }
    if (gid < N_NODES) g_off[gid] = s[tid];
    if (tid == SCAN_CHUNK - 1) g_bsum[blockIdx.x] = s[tid];
}

__global__ void k_scan2() {
    __shared__ int s[256];
    int tid = threadIdx.x;
    int v = (tid < NB) ? g_bsum[tid] : 0;
    s[tid] = v;
    __syncthreads();
    for (int d = 1; d < 256; d <<= 1) {
        int t = (tid >= d) ? s[tid - d] : 0;
        __syncthreads();
        s[tid] += t;
        __syncthreads();
    }
    if (tid < NB) g_bsum[tid] = s[tid] - v;
}

__global__ void k_scan3() {
    int i = blockIdx.x * blockDim.x + threadIdx.x;
    if (i < N_NODES) {
        int excl = g_off[i] - g_cnt[i] + g_bsum[i / SCAN_CHUNK];
        g_off[i] = excl;
        g_cur[i] = excl;
    }
}

// ---------------- scatter edges into CSR order (packed 8B stores) --------
__global__ void k_scatter(const int* __restrict__ edge_row,
                          const int* __restrict__ edge_col,
                          const float* __restrict__ edge_w) {
    int e = blockIdx.x * blockDim.x + threadIdx.x;
    if (e < N_EDGES) {
        int r = edge_row[e];
        int pos = atomicAdd(&g_cur[r], 1);
        int2 packed;
        packed.x = edge_col[e];
        packed.y = __float_as_int(edge_w[e]);
        g_edge[pos] = packed;
    }
}

// ---------------- CSR SpMM: one warp per row, fp16 gather, fp32 acc -------
// MODE 0: x=g_h0 -> y=g_h1; out  = ego1          (fp32 acc path exact)
// MODE 1: x=g_h1 -> y=g_h0; out += ego2
// MODE 2: x=g_h0;           out  = (out + ego3)/3
template <int MODE>
__global__ __launch_bounds__(256) void k_spmm(float* __restrict__ out) {
    int warp = (blockIdx.x * blockDim.x + threadIdx.x) >> 5;
    int lane = threadIdx.x & 31;
    if (warp >= N_NODES) return;

    int start = g_off[warp];
    int end   = (warp == N_NODES - 1) ? N_EDGES : g_off[warp + 1];

    const __half* xp = (MODE == 1) ? g_h1 : g_h0;
    const __half2* __restrict__ x2 = reinterpret_cast<const __half2*>(xp);
    float accx = 0.f, accy = 0.f;

    int e = start;
    // unroll x4 for memory-level parallelism on the L2 row gathers
    for (; e + 3 < end; e += 4) {
        int2 e0 = __ldg(&g_edge[e]);
        int2 e1 = __ldg(&g_edge[e + 1]);
        int2 e2 = __ldg(&g_edge[e + 2]);
        int2 e3 = __ldg(&g_edge[e + 3]);
        __half2 h0 = __ldg(&x2[(size_t)e0.x * 32 + lane]);
        __half2 h1 = __ldg(&x2[(size_t)e1.x * 32 + lane]);
        __half2 h2 = __ldg(&x2[(size_t)e2.x * 32 + lane]);
        __half2 h3 = __ldg(&x2[(size_t)e3.x * 32 + lane]);
        float2 a0 = __half22float2(h0);
        float2 a1 = __half22float2(h1);
        float2 a2 = __half22float2(h2);
        float2 a3 = __half22float2(h3);
        float w0 = __int_as_float(e0.y), w1 = __int_as_float(e1.y);
        float w2 = __int_as_float(e2.y), w3 = __int_as_float(e3.y);
        accx = fmaf(w0, a0.x, accx); accy = fmaf(w0, a0.y, accy);
        accx = fmaf(w1, a1.x, accx); accy = fmaf(w1, a1.y, accy);
        accx = fmaf(w2, a2.x, accx); accy = fmaf(w2, a2.y, accy);
        accx = fmaf(w3, a3.x, accx); accy = fmaf(w3, a3.y, accy);
    }
    for (; e < end; e++) {
        int2 ed = __ldg(&g_edge[e]);
        __half2 h = __ldg(&x2[(size_t)ed.x * 32 + lane]);
        float2 a = __half22float2(h);
        float w = __int_as_float(ed.y);
        accx = fmaf(w, a.x, accx);
        accy = fmaf(w, a.y, accy);
    }

    size_t idx = (size_t)warp * 32 + lane;
    float2* out2 = reinterpret_cast<float2*>(out);

    if (MODE == 0) {
        float2 v; v.x = accx; v.y = accy;
        out2[idx] = v;
        reinterpret_cast<__half2*>(g_h1)[idx] = __floats2half2_rn(accx, accy);
    } else if (MODE == 1) {
        float2 o = out2[idx];
        o.x += accx; o.y += accy;
        out2[idx] = o;
        reinterpret_cast<__half2*>(g_h0)[idx] = __floats2half2_rn(accx, accy);
    } else {
        float2 o = out2[idx];
        const float s = 1.0f / 3.0f;
        o.x = (o.x + accx) * s;
        o.y = (o.y + accy) * s;
        out2[idx] = o;
    }
}

// ---------------- launch ----------------
extern "C" void kernel_launch(void* const* d_in, const int* in_sizes, int n_in,
                              void* d_out, int out_size) {
    const float* user_emb = (const float*)d_in[0];
    const float* item_emb = (const float*)d_in[1];
    const float* edge_w   = (const float*)d_in[2];
    const int*   edge_row = (const int*)d_in[3];
    const int*   edge_col = (const int*)d_in[4];
    float* out = (float*)d_out;

    k_init<<<2048, 256>>>(user_emb, item_emb);
    k_hist<<<(N_EDGES + 255) / 256, 256>>>(edge_row);
    k_scan1<<<NB, SCAN_CHUNK>>>();
    k_scan2<<<1, 256>>>();
    k_scan3<<<(N_NODES + 255) / 256, 256>>>();
    k_scatter<<<(N_EDGES + 255) / 256, 256>>>(edge_row, edge_col, edge_w);

    const int SPMM_BLOCKS = (N_NODES * 32 + 255) / 256;   // one warp per row
    k_spmm<0><<<SPMM_BLOCKS, 256>>>(out);
    k_spmm<1><<<SPMM_BLOCKS, 256>>>(out);
    k_spmm<2><<<SPMM_BLOCKS, 256>>>(out);
}

// round 4
// speedup vs baseline: 1.1451x; 1.0307x over previous
#include <cuda_runtime.h>
#include <cuda_fp16.h>

#define NUM_USERS 100000
#define NUM_ITEMS 100000
#define N_NODES   200000
#define EMB       64
#define N_EDGES   3200000
#define SCAN_CHUNK 1024
#define NB ((N_NODES + SCAN_CHUNK - 1) / SCAN_CHUNK)   // 196

// ---------------- scratch (no allocations allowed) ----------------
__device__ int  g_cnt[N_NODES];
__device__ int  g_off[N_NODES];
__device__ int  g_cur[N_NODES];
__device__ int  g_bsum[NB];
__device__ __align__(16) int2   g_edge[N_EDGES];               // {col, w-bits} sorted by row
__device__ __align__(16) __half g_h0[(size_t)N_NODES * EMB];   // fp16 ping
__device__ __align__(16) __half g_h1[(size_t)N_NODES * EMB];   // fp16 pong

// -------- init + hist fused: ego->fp16 convert AND row histogram ----------
__global__ void k_init_hist(const float* __restrict__ user,
                            const float* __restrict__ item,
                            const int* __restrict__ edge_row) {
    int i = blockIdx.x * blockDim.x + threadIdx.x;
    int stride = gridDim.x * blockDim.x;
    const int NV4 = (N_NODES * EMB) / 4;
    const int UV4 = (NUM_USERS * EMB) / 4;
    const float4* u4 = reinterpret_cast<const float4*>(user);
    const float4* t4 = reinterpret_cast<const float4*>(item);
    uint2* h4 = reinterpret_cast<uint2*>(g_h0);
    for (int j = i; j < NV4; j += stride) {
        float4 f = (j < UV4) ? u4[j] : t4[j - UV4];
        __half2 a = __floats2half2_rn(f.x, f.y);
        __half2 b = __floats2half2_rn(f.z, f.w);
        uint2 p;
        p.x = *reinterpret_cast<unsigned*>(&a);
        p.y = *reinterpret_cast<unsigned*>(&b);
        h4[j] = p;
    }
    for (int j = i; j < N_NODES; j += stride)
        g_cnt[j] = 0;
    // histogram (after zeroing our slice; different blocks may interleave,
    // so zero and count must not race: use separate grid phase trick below)
}

// histogram must start only after all g_cnt zeroed -> separate kernel
__global__ void k_hist(const int* __restrict__ edge_row) {
    int e = blockIdx.x * blockDim.x + threadIdx.x;
    if (e < N_EDGES)
        atomicAdd(&g_cnt[edge_row[e]], 1);
}

// ---------------- 3-kernel exclusive scan over g_cnt ----------------
__global__ void k_scan1() {
    __shared__ int s[SCAN_CHUNK];
    int tid = threadIdx.x;
    int gid = blockIdx.x * SCAN_CHUNK + tid;
    int v = (gid < N_NODES) ? g_cnt[gid] : 0;
    s[tid] = v;
    __syncthreads();
    for (int d = 1; d < SCAN_CHUNK; d <<= 1) {
        int t = (tid >= d) ? s[tid - d] : 0;
        __syncthreads();
        s[tid] += t;
        __syncthreads();
    }
    if (gid < N_NODES) g_off[gid] = s[tid];
    if (tid == SCAN_CHUNK - 1) g_bsum[blockIdx.x] = s[tid];
}

__global__ void k_scan2() {
    __shared__ int s[256];
    int tid = threadIdx.x;
    int v = (tid < NB) ? g_bsum[tid] : 0;
    s[tid] = v;
    __syncthreads();
    for (int d = 1; d < 256; d <<= 1) {
        int t = (tid >= d) ? s[tid - d] : 0;
        __syncthreads();
        s[tid] += t;
        __syncthreads();
    }
    if (tid < NB) g_bsum[tid] = s[tid] - v;
}

__global__ void k_scan3() {
    int i = blockIdx.x * blockDim.x + threadIdx.x;
    if (i < N_NODES) {
        int excl = g_off[i] - g_cnt[i] + g_bsum[i / SCAN_CHUNK];
        g_off[i] = excl;
        g_cur[i] = excl;
    }
}

// ---------------- scatter edges into CSR order (packed 8B stores) --------
__global__ void k_scatter(const int* __restrict__ edge_row,
                          const int* __restrict__ edge_col,
                          const float* __restrict__ edge_w) {
    int e = blockIdx.x * blockDim.x + threadIdx.x;
    if (e < N_EDGES) {
        int r = edge_row[e];
        int pos = atomicAdd(&g_cur[r], 1);
        int2 packed;
        packed.x = edge_col[e];
        packed.y = __float_as_int(edge_w[e]);
        g_edge[pos] = packed;
    }
}

// ---------------- wide-gather CSR SpMM -----------------------------------
// One warp per row. Lane layout: g = lane>>3 (edge group 0..3), s = lane&7.
// Each lane gathers 16B (8 halves) of group-g's column row -> one LDG.128
// serves 4 edges. Cross-group reduction via shfl_xor(8), shfl_xor(16).
// MODE 0: x=g_h0 -> y=g_h1; out  = ego1
// MODE 1: x=g_h1 -> y=g_h0; out += ego2
// MODE 2: x=g_h0;           out  = (out + ego3)/3
template <int MODE>
__global__ __launch_bounds__(256) void k_spmm(float* __restrict__ out) {
    int warp = (blockIdx.x * blockDim.x + threadIdx.x) >> 5;
    int lane = threadIdx.x & 31;
    if (warp >= N_NODES) return;
    int g = lane >> 3;        // edge group within 4-edge batch
    int s = lane & 7;         // 16B chunk within 128B row

    int start = g_off[warp];
    int end   = (warp == N_NODES - 1) ? N_EDGES : g_off[warp + 1];

    const __half* xp = (MODE == 1) ? g_h1 : g_h0;
    const uint4* __restrict__ x4 = reinterpret_cast<const uint4*>(xp);

    float acc[8];
#pragma unroll
    for (int j = 0; j < 8; j++) acc[j] = 0.f;

    for (int e = start; e < end; e += 4) {
        int idx = e + g;
        // invalid groups read edge 0 with weight forced to 0
        bool valid = idx < end;
        int2 ed = __ldg(&g_edge[valid ? idx : start]);
        float w = valid ? __int_as_float(ed.y) : 0.f;
        uint4 hv = __ldg(&x4[(size_t)ed.x * 8 + s]);
        __half2 p0 = *reinterpret_cast<__half2*>(&hv.x);
        __half2 p1 = *reinterpret_cast<__half2*>(&hv.y);
        __half2 p2 = *reinterpret_cast<__half2*>(&hv.z);
        __half2 p3 = *reinterpret_cast<__half2*>(&hv.w);
        float2 f0 = __half22float2(p0);
        float2 f1 = __half22float2(p1);
        float2 f2 = __half22float2(p2);
        float2 f3 = __half22float2(p3);
        acc[0] = fmaf(w, f0.x, acc[0]);
        acc[1] = fmaf(w, f0.y, acc[1]);
        acc[2] = fmaf(w, f1.x, acc[2]);
        acc[3] = fmaf(w, f1.y, acc[3]);
        acc[4] = fmaf(w, f2.x, acc[4]);
        acc[5] = fmaf(w, f2.y, acc[5]);
        acc[6] = fmaf(w, f3.x, acc[6]);
        acc[7] = fmaf(w, f3.y, acc[7]);
    }

    // reduce across the 4 groups (lane bits 3 and 4)
#pragma unroll
    for (int j = 0; j < 8; j++) {
        acc[j] += __shfl_xor_sync(0xFFFFFFFF, acc[j], 8);
        acc[j] += __shfl_xor_sync(0xFFFFFFFF, acc[j], 16);
    }

    // epilogue: lanes of group 0 hold/write dims [8s .. 8s+7]
    if (g == 0) {
        float4* out4 = reinterpret_cast<float4*>(out);
        size_t ob = (size_t)warp * 16 + 2 * s;     // two float4 per lane

        if (MODE != 2) {
            // write fp16 y row
            __half2 y0 = __floats2half2_rn(acc[0], acc[1]);
            __half2 y1 = __floats2half2_rn(acc[2], acc[3]);
            __half2 y2 = __floats2half2_rn(acc[4], acc[5]);
            __half2 y3 = __floats2half2_rn(acc[6], acc[7]);
            uint4 pk;
            pk.x = *reinterpret_cast<unsigned*>(&y0);
            pk.y = *reinterpret_cast<unsigned*>(&y1);
            pk.z = *reinterpret_cast<unsigned*>(&y2);
            pk.w = *reinterpret_cast<unsigned*>(&y3);
            uint4* yp = reinterpret_cast<uint4*>((MODE == 0) ? g_h1 : g_h0);
            yp[(size_t)warp * 8 + s] = pk;
        }

        if (MODE == 0) {
            float4 a; a.x = acc[0]; a.y = acc[1]; a.z = acc[2]; a.w = acc[3];
            float4 b; b.x = acc[4]; b.y = acc[5]; b.z = acc[6]; b.w = acc[7];
            out4[ob] = a;
            out4[ob + 1] = b;
        } else if (MODE == 1) {
            float4 a = out4[ob], b = out4[ob + 1];
            a.x += acc[0]; a.y += acc[1]; a.z += acc[2]; a.w += acc[3];
            b.x += acc[4]; b.y += acc[5]; b.z += acc[6]; b.w += acc[7];
            out4[ob] = a;
            out4[ob + 1] = b;
        } else {
            const float sc = 1.0f / 3.0f;
            float4 a = out4[ob], b = out4[ob + 1];
            a.x = (a.x + acc[0]) * sc; a.y = (a.y + acc[1]) * sc;
            a.z = (a.z + acc[2]) * sc; a.w = (a.w + acc[3]) * sc;
            b.x = (b.x + acc[4]) * sc; b.y = (b.y + acc[5]) * sc;
            b.z = (b.z + acc[6]) * sc; b.w = (b.w + acc[7]) * sc;
            out4[ob] = a;
            out4[ob + 1] = b;
        }
    }
}

// ---------------- launch ----------------
extern "C" void kernel_launch(void* const* d_in, const int* in_sizes, int n_in,
                              void* d_out, int out_size) {
    const float* user_emb = (const float*)d_in[0];
    const float* item_emb = (const float*)d_in[1];
    const float* edge_w   = (const float*)d_in[2];
    const int*   edge_row = (const int*)d_in[3];
    const int*   edge_col = (const int*)d_in[4];
    float* out = (float*)d_out;

    k_init_hist<<<2048, 256>>>(user_emb, item_emb, edge_row);
    k_hist<<<(N_EDGES + 255) / 256, 256>>>(edge_row);
    k_scan1<<<NB, SCAN_CHUNK>>>();
    k_scan2<<<1, 256>>>();
    k_scan3<<<(N_NODES + 255) / 256, 256>>>();
    k_scatter<<<(N_EDGES + 255) / 256, 256>>>(edge_row, edge_col, edge_w);

    const int SPMM_BLOCKS = (N_NODES * 32 + 255) / 256;   // one warp per row
    k_spmm<0><<<SPMM_BLOCKS, 256>>>(out);
    k_spmm<1><<<SPMM_BLOCKS, 256>>>(out);
    k_spmm<2><<<SPMM_BLOCKS, 256>>>(out);
}

// round 7
// speedup vs baseline: 1.3013x; 1.1364x over previous
#include <cuda_runtime.h>
#include <cuda_fp16.h>

#define NUM_USERS 100000
#define NUM_ITEMS 100000
#define N_NODES   200000
#define EMB       64
#define N_EDGES   3200000
#define SCAN_CHUNK 1024
#define NB ((N_NODES + SCAN_CHUNK - 1) / SCAN_CHUNK)   // 196

// ---------------- scratch (no allocations allowed) ----------------
// NOTE: g_cnt is zero at module load, and k_scan23 re-zeroes it after use,
// so every invocation (first call and every graph replay) sees zeroed
// counters. This lets the histogram fuse with init.
__device__ int  g_cnt[N_NODES];
__device__ int  g_off[N_NODES];
__device__ int  g_cur[N_NODES];
__device__ int  g_bsum[NB];
__device__ __align__(16) int2   g_edge[N_EDGES];               // {col, w-bits} sorted by row
__device__ __align__(16) __half g_h0[(size_t)N_NODES * EMB];   // ego0
__device__ __align__(16) __half g_h1[(size_t)N_NODES * EMB];   // ego1
__device__ __align__(16) __half g_h2[(size_t)N_NODES * EMB];   // ego2

// -------- init + histogram fused (g_cnt guaranteed zero on entry) ---------
__global__ void k_init_hist(const float* __restrict__ user,
                            const float* __restrict__ item,
                            const int* __restrict__ edge_row) {
    int i = blockIdx.x * blockDim.x + threadIdx.x;
    int stride = gridDim.x * blockDim.x;
    const int NV4 = (N_NODES * EMB) / 4;
    const int UV4 = (NUM_USERS * EMB) / 4;
    const float4* u4 = reinterpret_cast<const float4*>(user);
    const float4* t4 = reinterpret_cast<const float4*>(item);
    uint2* h4 = reinterpret_cast<uint2*>(g_h0);
    for (int j = i; j < NV4; j += stride) {
        float4 f = (j < UV4) ? u4[j] : t4[j - UV4];
        __half2 a = __floats2half2_rn(f.x, f.y);
        __half2 b = __floats2half2_rn(f.z, f.w);
        uint2 p;
        p.x = *reinterpret_cast<unsigned*>(&a);
        p.y = *reinterpret_cast<unsigned*>(&b);
        h4[j] = p;
    }
    for (int e = i; e < N_EDGES; e += stride)
        atomicAdd(&g_cnt[__ldg(&edge_row[e])], 1);
}

// ---------------- scan stage 1: per-chunk inclusive scan ------------------
__global__ void k_scan1() {
    __shared__ int s[SCAN_CHUNK];
    int tid = threadIdx.x;
    int gid = blockIdx.x * SCAN_CHUNK + tid;
    int v = (gid < N_NODES) ? g_cnt[gid] : 0;
    s[tid] = v;
    __syncthreads();
    for (int d = 1; d < SCAN_CHUNK; d <<= 1) {
        int t = (tid >= d) ? s[tid - d] : 0;
        __syncthreads();
        s[tid] += t;
        __syncthreads();
    }
    if (gid < N_NODES) g_off[gid] = s[tid];
    if (tid == SCAN_CHUNK - 1) g_bsum[blockIdx.x] = s[tid];
}

// ---------------- scan stage 2+3 fused + g_cnt reset ----------------------
// Each block re-scans the 196 block sums locally (cheap, L2-resident),
// then finalizes exclusive offsets for its 256 nodes and zeroes g_cnt.
__global__ void k_scan23() {
    __shared__ int s[256];
    int tid = threadIdx.x;
    s[tid] = (tid < NB) ? g_bsum[tid] : 0;
    __syncthreads();
    for (int d = 1; d < 256; d <<= 1) {
        int t = (tid >= d) ? s[tid - d] : 0;
        __syncthreads();
        s[tid] += t;
        __syncthreads();
    }
    int i = blockIdx.x * blockDim.x + tid;
    if (i < N_NODES) {
        int chunk = i / SCAN_CHUNK;
        int bpre = (chunk == 0) ? 0 : s[chunk - 1];
        int excl = g_off[i] - g_cnt[i] + bpre;
        g_off[i] = excl;
        g_cur[i] = excl;
        g_cnt[i] = 0;              // restore invariant for next replay
    }
}

// ---------------- scatter edges into CSR order (packed 8B stores) --------
__global__ void k_scatter(const int* __restrict__ edge_row,
                          const int* __restrict__ edge_col,
                          const float* __restrict__ edge_w) {
    int e = blockIdx.x * blockDim.x + threadIdx.x;
    if (e < N_EDGES) {
        int r = __ldg(&edge_row[e]);
        int pos = atomicAdd(&g_cur[r], 1);
        int2 packed;
        packed.x = __ldg(&edge_col[e]);
        packed.y = __float_as_int(__ldg(&edge_w[e]));
        g_edge[pos] = packed;
    }
}

// ---------------- wide-gather CSR SpMM, software-pipelined ----------------
// One warp per row. g = lane>>3 selects edge within 4-edge batch,
// s = lane&7 selects the 16B chunk of the 128B fp16 row.
// Next batch's edge records are prefetched while the current gather is
// outstanding, halving the per-iteration dependent-latency chain.
// MODE 0: x=g_h0 -> y=g_h1
// MODE 1: x=g_h1 -> y=g_h2
// MODE 2: x=g_h2;  out = (h1 + h2 + acc)/3   (single out write)
template <int MODE>
__global__ __launch_bounds__(256) void k_spmm(float* __restrict__ out) {
    int warp = (blockIdx.x * blockDim.x + threadIdx.x) >> 5;
    int lane = threadIdx.x & 31;
    if (warp >= N_NODES) return;
    int g = lane >> 3;
    int s = lane & 7;

    int start = g_off[warp];
    int end   = (warp == N_NODES - 1) ? N_EDGES : g_off[warp + 1];

    const __half* xp = (MODE == 0) ? g_h0 : (MODE == 1) ? g_h1 : g_h2;
    const uint4* __restrict__ x4 = reinterpret_cast<const uint4*>(xp);

    float acc[8];
#pragma unroll
    for (int j = 0; j < 8; j++) acc[j] = 0.f;

    // prime the pipeline
    bool v = (start + g) < end;
    int2 ed;
    if (start < end)
        ed = __ldg(&g_edge[v ? (start + g) : (end - 1)]);

    for (int e = start; e < end; e += 4) {
        int2 cur = ed;
        float w = v ? __int_as_float(cur.y) : 0.f;
        int ne = e + 4;
        if (ne < end) {                               // prefetch next batch
            v = (ne + g) < end;
            ed = __ldg(&g_edge[v ? (ne + g) : (end - 1)]);
        }
        uint4 hv = __ldg(&x4[cur.x * 8 + s]);
        __half2 p0 = *reinterpret_cast<__half2*>(&hv.x);
        __half2 p1 = *reinterpret_cast<__half2*>(&hv.y);
        __half2 p2 = *reinterpret_cast<__half2*>(&hv.z);
        __half2 p3 = *reinterpret_cast<__half2*>(&hv.w);
        float2 f0 = __half22float2(p0);
        float2 f1 = __half22float2(p1);
        float2 f2 = __half22float2(p2);
        float2 f3 = __half22float2(p3);
        acc[0] = fmaf(w, f0.x, acc[0]);
        acc[1] = fmaf(w, f0.y, acc[1]);
        acc[2] = fmaf(w, f1.x, acc[2]);
        acc[3] = fmaf(w, f1.y, acc[3]);
        acc[4] = fmaf(w, f2.x, acc[4]);
        acc[5] = fmaf(w, f2.y, acc[5]);
        acc[6] = fmaf(w, f3.x, acc[6]);
        acc[7] = fmaf(w, f3.y, acc[7]);
    }

    // reduce across the 4 edge groups
#pragma unroll
    for (int j = 0; j < 8; j++) {
        acc[j] += __shfl_xor_sync(0xFFFFFFFF, acc[j], 8);
        acc[j] += __shfl_xor_sync(0xFFFFFFFF, acc[j], 16);
    }

    if (g == 0) {
        int ridx = warp * 8 + s;                 // uint4 index of this 16B chunk
        if (MODE != 2) {
            __half2 y0 = __floats2half2_rn(acc[0], acc[1]);
            __half2 y1 = __floats2half2_rn(acc[2], acc[3]);
            __half2 y2 = __floats2half2_rn(acc[4], acc[5]);
            __half2 y3 = __floats2half2_rn(acc[6], acc[7]);
            uint4 pk;
            pk.x = *reinterpret_cast<unsigned*>(&y0);
            pk.y = *reinterpret_cast<unsigned*>(&y1);
            pk.z = *reinterpret_cast<unsigned*>(&y2);
            pk.w = *reinterpret_cast<unsigned*>(&y3);
            uint4* yp = reinterpret_cast<uint4*>((MODE == 0) ? g_h1 : g_h2);
            yp[ridx] = pk;
        } else {
            // out = (ego1 + ego2 + ego3) / 3
            uint4 a1 = __ldg(&reinterpret_cast<const uint4*>(g_h1)[ridx]);
            uint4 a2 = __ldg(&reinterpret_cast<const uint4*>(g_h2)[ridx]);
            const float sc = 1.0f / 3.0f;
            float4 o0, o1;
            float2 t;
            t = __half22float2(*reinterpret_cast<__half2*>(&a1.x));
            o0.x = t.x; o0.y = t.y;
            t = __half22float2(*reinterpret_cast<__half2*>(&a1.y));
            o0.z = t.x; o0.w = t.y;
            t = __half22float2(*reinterpret_cast<__half2*>(&a1.z));
            o1.x = t.x; o1.y = t.y;
            t = __half22float2(*reinterpret_cast<__half2*>(&a1.w));
            o1.z = t.x; o1.w = t.y;
            t = __half22float2(*reinterpret_cast<__half2*>(&a2.x));
            o0.x += t.x; o0.y += t.y;
            t = __half22float2(*reinterpret_cast<__half2*>(&a2.y));
            o0.z += t.x; o0.w += t.y;
            t = __half22float2(*reinterpret_cast<__half2*>(&a2.z));
            o1.x += t.x; o1.y += t.y;
            t = __half22float2(*reinterpret_cast<__half2*>(&a2.w));
            o1.z += t.x; o1.w += t.y;
            o0.x = (o0.x + acc[0]) * sc; o0.y = (o0.y + acc[1]) * sc;
            o0.z = (o0.z + acc[2]) * sc; o0.w = (o0.w + acc[3]) * sc;
            o1.x = (o1.x + acc[4]) * sc; o1.y = (o1.y + acc[5]) * sc;
            o1.z = (o1.z + acc[6]) * sc; o1.w = (o1.w + acc[7]) * sc;
            float4* out4 = reinterpret_cast<float4*>(out);
            out4[2 * ridx]     = o0;
            out4[2 * ridx + 1] = o1;
        }
    }
}

// ---------------- launch ----------------
extern "C" void kernel_launch(void* const* d_in, const int* in_sizes, int n_in,
                              void* d_out, int out_size) {
    const float* user_emb = (const float*)d_in[0];
    const float* item_emb = (const float*)d_in[1];
    const float* edge_w   = (const float*)d_in[2];
    const int*   edge_row = (const int*)d_in[3];
    const int*   edge_col = (const int*)d_in[4];
    float* out = (float*)d_out;

    k_init_hist<<<2048, 256>>>(user_emb, item_emb, edge_row);
    k_scan1<<<NB, SCAN_CHUNK>>>();
    k_scan23<<<(N_NODES + 255) / 256, 256>>>();
    k_scatter<<<(N_EDGES + 255) / 256, 256>>>(edge_row, edge_col, edge_w);

    const int SPMM_BLOCKS = (N_NODES * 32 + 255) / 256;   // one warp per row
    k_spmm<0><<<SPMM_BLOCKS, 256>>>(out);
    k_spmm<1><<<SPMM_BLOCKS, 256>>>(out);
    k_spmm<2><<<SPMM_BLOCKS, 256>>>(out);
}